// round 8
// baseline (speedup 1.0000x reference)
#include <cuda_runtime.h>
#include <stdint.h>

#define DI __device__ __forceinline__

// ===================== device scratch (no allocations) =====================
// U/V stored in quad-permuted channel order (see quadpos)
__device__ float g_Upp[128*64*128];
__device__ float g_Vpp[128*64*128];
__device__ float g_Upv[128*64*128];
__device__ float g_Vpv[128*14*128];
__device__ float g_EppT[128*64*64];   // transposed: [b][c][r]
__device__ float g_EpvT[128*64*64];   // transposed: [b][c][r]

// pre-transposed tf32 weight images, quad-permuted k, stride 144 (176 for FO1)
__device__ __align__(16) float g_W2pp[128*144];
__device__ __align__(16) float g_W3pp[64*144];
__device__ __align__(16) float g_W2pv[128*144];
__device__ __align__(16) float g_W3pv[64*144];
__device__ __align__(16) float g_FO1 [128*176];
__device__ __align__(16) float g_FO2 [128*144];
__device__ __align__(16) float g_FO3 [64*144];

// ===================== helpers =====================
DI float to_tf32(float x){ float r; asm("cvt.rna.tf32.f32 %0, %1;" : "=f"(r) : "f"(x)); return r; }
// quad layout: for channel k, float offset within a row.
// Groups of 16 channels (2 MMA k-steps); thread tg's four fragments contiguous:
// [kstep even lo, kstep even hi, kstep odd lo, kstep odd hi]
DI int quadpos(int k){
    int kt = k >> 3, p = k & 3, hi = (k >> 2) & 1;
    return (kt >> 1)*16 + p*4 + (kt & 1)*2 + hi;
}
DI void barh(int id){ asm volatile("bar.sync %0, %1;" :: "r"(id), "r"(256) : "memory"); }

DI void mma_tf32(float* d, uint32_t a0, uint32_t a1, uint32_t a2, uint32_t a3,
                 uint32_t b0, uint32_t b1){
    asm volatile(
        "mma.sync.aligned.m16n8k8.row.col.f32.tf32.tf32.f32 "
        "{%0,%1,%2,%3}, {%4,%5,%6,%7}, {%8,%9}, {%0,%1,%2,%3};"
        : "+f"(d[0]), "+f"(d[1]), "+f"(d[2]), "+f"(d[3])
        : "r"(a0), "r"(a1), "r"(a2), "r"(a3), "r"(b0), "r"(b1));
}

// Warp GEMM on quad-interleaved tf32 buffers with LDS.128.
// MT m-tiles (16 rows at row0+mt*16) x NT n-tiles (8 cols from ncol0). acc[MT*NT*4].
// KT2 = K/16. Strides sa,sw in floats, ≡ 16 (mod 32).
template<int KT2, int MT, int NT>
DI void wgemm4(const float* A, int sa, const float* W, int sw,
               int row0, int ncol0, int lane, float* acc)
{
    const int g = lane >> 2, tg = lane & 3;
#pragma unroll
    for (int i = 0; i < MT*NT*4; i++) acc[i] = 0.f;
#pragma unroll
    for (int kt2 = 0; kt2 < KT2; kt2++){
        const int jo = kt2*16 + tg*4;
        float4 av[2*MT];
#pragma unroll
        for (int mt = 0; mt < MT; mt++){
            av[2*mt]   = *(const float4*)(A + (row0 + mt*16 + g)*sa + jo);
            av[2*mt+1] = *(const float4*)(A + (row0 + mt*16 + g + 8)*sa + jo);
        }
        float4 bv[NT];
#pragma unroll
        for (int nt = 0; nt < NT; nt++)
            bv[nt] = *(const float4*)(W + (ncol0 + nt*8 + g)*sw + jo);
#pragma unroll
        for (int nt = 0; nt < NT; nt++){
#pragma unroll
            for (int mt = 0; mt < MT; mt++){
                float* a = acc + (mt*NT+nt)*4;
                mma_tf32(a, __float_as_uint(av[2*mt].x), __float_as_uint(av[2*mt+1].x),
                            __float_as_uint(av[2*mt].y), __float_as_uint(av[2*mt+1].y),
                            __float_as_uint(bv[nt].x),   __float_as_uint(bv[nt].y));
                mma_tf32(a, __float_as_uint(av[2*mt].z), __float_as_uint(av[2*mt+1].z),
                            __float_as_uint(av[2*mt].w), __float_as_uint(av[2*mt+1].w),
                            __float_as_uint(bv[nt].z),   __float_as_uint(bv[nt].w));
            }
        }
    }
}

// Epilogue: relu(acc+bias) -> tf32, stored quad-permuted into O (stride so)
template<int MT, int NT>
DI void epi_store4(const float* acc, float* O, int so,
                   int row0, int ncol0, int lane, const float* bias)
{
    const int g = lane >> 2, tg = lane & 3;
#pragma unroll
    for (int mt = 0; mt < MT; mt++){
#pragma unroll
        for (int nt = 0; nt < NT; nt++){
            int cb = ncol0 + nt*8;
            int c0 = cb + 2*tg, c1 = c0 + 1;
            int q0 = quadpos(c0), q1 = quadpos(c1);
            float b0 = bias[c0], b1 = bias[c1];
            const float* a = acc + (mt*NT+nt)*4;
            int r = row0 + mt*16 + g;
            O[r*so + q0]     = to_tf32(fmaxf(a[0]+b0, 0.f));
            O[r*so + q1]     = to_tf32(fmaxf(a[1]+b1, 0.f));
            O[(r+8)*so + q0] = to_tf32(fmaxf(a[2]+b0, 0.f));
            O[(r+8)*so + q1] = to_tf32(fmaxf(a[3]+b1, 0.f));
        }
    }
}

// ===================== prep: transpose + tf32 + quad-permute weights =====================
__global__ void prep_kernel(const float* __restrict__ w2pp, const float* __restrict__ w3pp,
                            const float* __restrict__ w2pv, const float* __restrict__ w3pv,
                            const float* __restrict__ w1o,  const float* __restrict__ w2o,
                            const float* __restrict__ w3o)
{
    int T = blockDim.x * gridDim.x, t0 = blockIdx.x * blockDim.x + threadIdx.x;
    for (int i = t0; i < 128*128; i += T){ int n = i>>7, k = i&127;
        g_W2pp[n*144 + quadpos(k)] = to_tf32(w2pp[k*128+n]); }
    for (int i = t0; i < 64*128; i += T){ int n = i>>7, k = i&127;
        g_W3pp[n*144 + quadpos(k)] = to_tf32(w3pp[k*64+n]); }
    for (int i = t0; i < 128*128; i += T){ int n = i>>7, k = i&127;
        g_W2pv[n*144 + quadpos(k)] = to_tf32(w2pv[k*128+n]); }
    for (int i = t0; i < 64*128; i += T){ int n = i>>7, k = i&127;
        g_W3pv[n*144 + quadpos(k)] = to_tf32(w3pv[k*64+n]); }
    for (int i = t0; i < 128*160; i += T){ int n = i/160, k = i - n*160;
        g_FO1[n*176 + quadpos(k)] = to_tf32(w1o[k*128+n]); }
    for (int i = t0; i < 128*128; i += T){ int n = i>>7, k = i&127;
        g_FO2[n*144 + quadpos(k)] = to_tf32(w2o[k*128+n]); }
    for (int i = t0; i < 64*128; i += T){ int n = i>>7, k = i&127;
        g_FO3[n*144 + quadpos(k)] = to_tf32(w3o[k*64+n]); }
}

// ===================== precompute: factorized first layers (fp32, quad-permuted out) ==========
__global__ void precompute_kernel(const float* __restrict__ x, const float* __restrict__ y,
                                  const float* __restrict__ w1,   const float* __restrict__ b1,
                                  const float* __restrict__ w1pv, const float* __restrict__ b1pv)
{
    __shared__ float xs[32][65];
    const int b = blockIdx.x, tid = threadIdx.x;
    for (int idx = tid; idx < 2048; idx += 256){
        int p = idx >> 6, n = idx & 63;
        xs[p][n] = x[(b*32 + p)*64 + n];
    }
    __syncthreads();
    for (int idx = tid; idx < 8192; idx += 256){
        int n = idx >> 7, h = idx & 127;
        float u = b1[h], v = 0.f, upv = b1pv[h];
#pragma unroll
        for (int p = 0; p < 32; p++){
            float xv = xs[p][n];
            u   = fmaf(xv, w1[p*128 + h], u);
            v   = fmaf(xv, w1[(32+p)*128 + h], v);
            upv = fmaf(xv, w1pv[p*128 + h], upv);
        }
        int ph = quadpos(h);
        g_Upp[(b*64+n)*128 + ph] = u;
        g_Vpp[(b*64+n)*128 + ph] = v;
        g_Upv[(b*64+n)*128 + ph] = upv;
    }
    for (int idx = tid; idx < 1792; idx += 256){
        int v = idx >> 7, h = idx & 127;
        float s = 0.f;
#pragma unroll
        for (int sv = 0; sv < 14; sv++)
            s = fmaf(y[(b*14+sv)*14 + v], w1pv[(32+sv)*128 + h], s);
        g_Vpv[(b*14+v)*128 + quadpos(h)] = s;
    }
}

// ===================== edge kernels: persistent, 512 thr, two half-CTAs =====================
// smem (bytes): W2[128x144] | W3[64x144] | BUF 2x[64x144] | b2 | b3 | part 2x128f
#define EP_W2   0
#define EP_W3   73728
#define EP_BUF  110592
#define EP_B2   184320
#define EP_B3   184832
#define EP_PT   185088
#define EP_SM   186112

__global__ __launch_bounds__(512, 1) void pp_kernel(const float* __restrict__ b2v,
                                                    const float* __restrict__ b3v)
{
    extern __shared__ char sm[];
    float* W2   = (float*)(sm + EP_W2);
    float* W3   = (float*)(sm + EP_W3);
    float* bias2= (float*)(sm + EP_B2);
    float* bias3= (float*)(sm + EP_B3);
    const int tid = threadIdx.x;
    const int half = tid >> 8, htid = tid & 255;
    const int hw = (tid >> 5) & 7, lane = tid & 31;
    const int g = lane >> 2, tg = lane & 3;
    const int rg = hw & 1, cg = hw >> 1;         // 2 row-groups x 4 col-groups (per half)
    float* BUF  = (float*)(sm + EP_BUF + half*36864);
    float* part = (float*)(sm + EP_PT  + half*512);
    const int barid = 1 + half;

    for (int i = tid; i < 4608; i += 512) ((float4*)W2)[i] = ((const float4*)g_W2pp)[i];
    for (int i = tid; i < 2304; i += 512) ((float4*)W3)[i] = ((const float4*)g_W3pp)[i];
    if (tid < 128) bias2[tid] = b2v[tid];
    if (tid < 64)  bias3[tid] = b3v[tid];
    __syncthreads();

    const int c4 = htid & 31;                    // float4 chunk within row
    const int r0 = htid >> 5;                    // base row (8 rows per thread)
    const int hidx = blockIdx.x*2 + half, nh = gridDim.x*2;
    const int tstart = (int)((long long)8192*hidx/nh);
    const int tend   = (int)((long long)8192*(hidx+1)/nh);

    for (int t = tstart; t < tend; t++){
        const int b = t >> 6, r = t & 63;
        const float* Ur = g_Upp + ((size_t)b*64 + r)*128;
        const float* Vb = g_Vpp + (size_t)b*64*128;
        float4 u = *(const float4*)(Ur + c4*4);  // hoisted: fixed per thread
#pragma unroll
        for (int it = 0; it < 8; it++){
            int s = r0 + it*8;
            float4 v = *(const float4*)(Vb + s*128 + c4*4);
            float4 h;
            h.x = to_tf32(fmaxf(u.x + v.x, 0.f));
            h.y = to_tf32(fmaxf(u.y + v.y, 0.f));
            h.z = to_tf32(fmaxf(u.z + v.z, 0.f));
            h.w = to_tf32(fmaxf(u.w + v.w, 0.f));
            *(float4*)(BUF + s*144 + c4*4) = h;
        }
        barh(barid);
        {   // layer 2: 64x128, in-place BUF
            float acc[32];
            wgemm4<8,2,4>(BUF, 144, W2, 144, rg*32, cg*32, lane, acc);
            barh(barid);
            epi_store4<2,4>(acc, BUF, 144, rg*32, cg*32, lane, bias2);
        }
        barh(barid);
        {   // layer 3: 64x64 + self-excluded column reduce
            float acc3[16];
            wgemm4<8,2,2>(BUF, 144, W3, 144, rg*32, cg*16, lane, acc3);
#pragma unroll
            for (int nt = 0; nt < 2; nt++){
                int c = cg*16 + nt*8 + tg*2;
                float b0 = bias3[c], b1 = bias3[c+1];
                float t0 = 0.f, t1 = 0.f;
#pragma unroll
                for (int mt = 0; mt < 2; mt++){
                    int ra = rg*32 + mt*16 + g, rb = ra + 8;
                    bool z1 = (ra == r), z2 = (rb == r);
                    const float* a = acc3 + (mt*2+nt)*4;
                    t0 += (z1 ? 0.f : fmaxf(a[0]+b0, 0.f)) + (z2 ? 0.f : fmaxf(a[2]+b0, 0.f));
                    t1 += (z1 ? 0.f : fmaxf(a[1]+b1, 0.f)) + (z2 ? 0.f : fmaxf(a[3]+b1, 0.f));
                }
#pragma unroll
                for (int m = 4; m < 32; m <<= 1){
                    t0 += __shfl_xor_sync(0xffffffffu, t0, m);
                    t1 += __shfl_xor_sync(0xffffffffu, t1, m);
                }
                if (g == 0){ part[rg*64 + c] = t0; part[rg*64 + c + 1] = t1; }
            }
        }
        barh(barid);
        if (htid < 64){
            float ssum = part[htid] + part[64 + htid];
            g_EppT[((size_t)b*64 + htid)*64 + r] = ssum;
        }
        barh(barid);
    }
}

__global__ __launch_bounds__(512, 1) void pv_kernel(const float* __restrict__ b2v,
                                                    const float* __restrict__ b3v)
{
    extern __shared__ char sm[];
    float* W2   = (float*)(sm + EP_W2);
    float* W3   = (float*)(sm + EP_W3);
    float* bias2= (float*)(sm + EP_B2);
    float* bias3= (float*)(sm + EP_B3);
    const int tid = threadIdx.x;
    const int half = tid >> 8, htid = tid & 255;
    const int hw = (tid >> 5) & 7, lane = tid & 31;
    const int g = lane >> 2, tg = lane & 3;
    const int rg = hw & 1, cg = hw >> 1;
    float* BUF = (float*)(sm + EP_BUF + half*36864);
    const int barid = 1 + half;

    for (int i = tid; i < 4608; i += 512) ((float4*)W2)[i] = ((const float4*)g_W2pv)[i];
    for (int i = tid; i < 2304; i += 512) ((float4*)W3)[i] = ((const float4*)g_W3pv)[i];
    if (tid < 128) bias2[tid] = b2v[tid];
    if (tid < 64)  bias3[tid] = b3v[tid];
    __syncthreads();

    const int c4 = htid & 31;
    const int r0 = htid >> 5;
    const int hidx = blockIdx.x*2 + half, nh = gridDim.x*2;
    const int tstart = (int)((long long)2048*hidx/nh);
    const int tend   = (int)((long long)2048*(hidx+1)/nh);

    for (int t = tstart; t < tend; t++){
        const int b = t >> 4, grp = t & 15;      // receivers grp*4 .. grp*4+3
        const float* Ub = g_Upv + ((size_t)b*64 + grp*4)*128;
        const float* Vb = g_Vpv + (size_t)b*14*128;
#pragma unroll
        for (int it = 0; it < 8; it++){
            int row = r0 + it*8;                 // ri = row>>4, vv = row&15
            int ri = row >> 4, vv = row & 15;
            float4 h; h.x = h.y = h.z = h.w = 0.f;
            if (vv < 14){
                float4 u = *(const float4*)(Ub + ri*128 + c4*4);
                float4 v = *(const float4*)(Vb + vv*128 + c4*4);
                h.x = to_tf32(fmaxf(u.x + v.x, 0.f));
                h.y = to_tf32(fmaxf(u.y + v.y, 0.f));
                h.z = to_tf32(fmaxf(u.z + v.z, 0.f));
                h.w = to_tf32(fmaxf(u.w + v.w, 0.f));
            }
            *(float4*)(BUF + row*144 + c4*4) = h;
        }
        barh(barid);
        {
            float acc[32];
            wgemm4<8,2,4>(BUF, 144, W2, 144, rg*32, cg*32, lane, acc);
            barh(barid);
            epi_store4<2,4>(acc, BUF, 144, rg*32, cg*32, lane, bias2);
        }
        barh(barid);
        {   // layer 3 + per-receiver reduce (receiver = grp*4 + rg*2 + mt)
            float acc3[16];
            wgemm4<8,2,2>(BUF, 144, W3, 144, rg*32, cg*16, lane, acc3);
            bool z2 = (g >= 6);                  // row vv=g+8 is pad when >=14
#pragma unroll
            for (int mt = 0; mt < 2; mt++){
                int recv = grp*4 + rg*2 + mt;
#pragma unroll
                for (int nt = 0; nt < 2; nt++){
                    int c = cg*16 + nt*8 + tg*2;
                    float b0 = bias3[c], b1 = bias3[c+1];
                    const float* a = acc3 + (mt*2+nt)*4;
                    float t0 = fmaxf(a[0]+b0, 0.f) + (z2 ? 0.f : fmaxf(a[2]+b0, 0.f));
                    float t1 = fmaxf(a[1]+b1, 0.f) + (z2 ? 0.f : fmaxf(a[3]+b1, 0.f));
#pragma unroll
                    for (int m = 4; m < 32; m <<= 1){
                        t0 += __shfl_xor_sync(0xffffffffu, t0, m);
                        t1 += __shfl_xor_sync(0xffffffffu, t1, m);
                    }
                    if (g == 0){
                        g_EpvT[((size_t)b*64 + c)*64 + recv]     = t0;
                        g_EpvT[((size_t)b*64 + c + 1)*64 + recv] = t1;
                    }
                }
            }
        }
        barh(barid);
    }
}

// ===================== object MLP + pool + classifier: 1 graph/block =====================
// C[64x176] (H3 overlays, stride 144) | Wbuf[128x176] | H2[64x144] | misc
#define OB_C   0
#define OB_W   45056
#define OB_H2  135168
#define OB_B1  172032
#define OB_B2  172544
#define OB_B3  173056
#define OB_FCB 173312
#define OB_PT  173344
#define OB_PL  173856
#define OB_SM  174112

__global__ __launch_bounds__(256) void obj_kernel(const float* __restrict__ x,
                                                  const float* __restrict__ b1v,
                                                  const float* __restrict__ b2v,
                                                  const float* __restrict__ b3v,
                                                  const float* __restrict__ fcw,
                                                  const float* __restrict__ fcb,
                                                  float* __restrict__ out)
{
    extern __shared__ char sm[];
    float* C    = (float*)(sm + OB_C);
    float* Wbuf = (float*)(sm + OB_W);
    float* H2   = (float*)(sm + OB_H2);
    float* H3   = (float*)(sm + OB_C);
    float* bias1  = (float*)(sm + OB_B1);
    float* bias2  = (float*)(sm + OB_B2);
    float* bias3  = (float*)(sm + OB_B3);
    float* fcbs   = (float*)(sm + OB_FCB);
    float* part   = (float*)(sm + OB_PT);
    float* pooled = (float*)(sm + OB_PL);
    const int tid = threadIdx.x, wid = tid >> 5, lane = tid & 31;
    const int g = lane >> 2, tg = lane & 3;
    const int rg = wid & 1, cg = wid >> 1;
    const int bg = blockIdx.x;

    for (int i = tid; i < 5632; i += 256) ((float4*)Wbuf)[i] = ((const float4*)g_FO1)[i];
    if (tid < 128) bias1[tid] = b1v[tid];
    if (tid < 128) bias2[tid] = b2v[tid];
    if (tid < 64)  bias3[tid] = b3v[tid];
    if (tid < 5)   fcbs[tid]  = fcb[tid];
    // C[n][quadpos(k)], K=160
    for (int i = tid; i < 160*64; i += 256){
        int k = i >> 6, n = i & 63;              // consecutive threads -> consecutive n
        float v;
        if (k < 32)      v = x[(bg*32 + k)*64 + n];
        else if (k < 96) v = g_EppT[((size_t)bg*64 + (k-32))*64 + n];
        else             v = g_EpvT[((size_t)bg*64 + (k-96))*64 + n];
        C[n*176 + quadpos(k)] = to_tf32(v);
    }
    __syncthreads();
    {   // layer 1
        float acc[32];
        wgemm4<10,2,4>(C, 176, Wbuf, 176, rg*32, cg*32, lane, acc);
        epi_store4<2,4>(acc, H2, 144, rg*32, cg*32, lane, bias1);
    }
    __syncthreads();
    for (int i = tid; i < 4608; i += 256) ((float4*)Wbuf)[i] = ((const float4*)g_FO2)[i];
    __syncthreads();
    {   // layer 2 (H3 overlays C)
        float acc[32];
        wgemm4<8,2,4>(H2, 144, Wbuf, 144, rg*32, cg*32, lane, acc);
        __syncthreads();
        epi_store4<2,4>(acc, H3, 144, rg*32, cg*32, lane, bias2);
    }
    __syncthreads();
    for (int i = tid; i < 2304; i += 256) ((float4*)Wbuf)[i] = ((const float4*)g_FO3)[i];
    __syncthreads();
    {   // layer 3 + pooling reduce
        float acc[16];
        wgemm4<8,2,2>(H3, 144, Wbuf, 144, rg*32, cg*16, lane, acc);
#pragma unroll
        for (int nt = 0; nt < 2; nt++){
            int c = cg*16 + nt*8 + tg*2;
            float b0 = bias3[c], b1 = bias3[c+1];
            float t0 = 0.f, t1 = 0.f;
#pragma unroll
            for (int mt = 0; mt < 2; mt++){
                const float* a = acc + (mt*2+nt)*4;
                t0 += fmaxf(a[0]+b0, 0.f) + fmaxf(a[2]+b0, 0.f);
                t1 += fmaxf(a[1]+b1, 0.f) + fmaxf(a[3]+b1, 0.f);
            }
#pragma unroll
            for (int m = 4; m < 32; m <<= 1){
                t0 += __shfl_xor_sync(0xffffffffu, t0, m);
                t1 += __shfl_xor_sync(0xffffffffu, t1, m);
            }
            if (g == 0){ part[rg*64 + c] = t0; part[rg*64 + c + 1] = t1; }
        }
    }
    __syncthreads();
    if (tid < 64) pooled[tid] = part[tid] + part[64 + tid];
    __syncthreads();
    if (tid < 5){
        float s = fcbs[tid];
#pragma unroll 8
        for (int j = 0; j < 64; j++)
            s = fmaf(pooled[j], fcw[j*5 + tid], s);
        out[bg*5 + tid] = s;
    }
}

// ===================== launch =====================
extern "C" void kernel_launch(void* const* d_in, const int* in_sizes, int n_in,
                              void* d_out, int out_size)
{
    const float* x       = (const float*)d_in[0];
    const float* y       = (const float*)d_in[1];
    const float* fr1_w   = (const float*)d_in[2];
    const float* fr1_b   = (const float*)d_in[3];
    const float* fr2_w   = (const float*)d_in[4];
    const float* fr2_b   = (const float*)d_in[5];
    const float* fr3_w   = (const float*)d_in[6];
    const float* fr3_b   = (const float*)d_in[7];
    const float* fr1pv_w = (const float*)d_in[8];
    const float* fr1pv_b = (const float*)d_in[9];
    const float* fr2pv_w = (const float*)d_in[10];
    const float* fr2pv_b = (const float*)d_in[11];
    const float* fr3pv_w = (const float*)d_in[12];
    const float* fr3pv_b = (const float*)d_in[13];
    const float* fo1_w   = (const float*)d_in[14];
    const float* fo1_b   = (const float*)d_in[15];
    const float* fo2_w   = (const float*)d_in[16];
    const float* fo2_b   = (const float*)d_in[17];
    const float* fo3_w   = (const float*)d_in[18];
    const float* fo3_b   = (const float*)d_in[19];
    const float* fc_w    = (const float*)d_in[20];
    const float* fc_b    = (const float*)d_in[21];
    float* out = (float*)d_out;

    cudaFuncSetAttribute(pp_kernel,  cudaFuncAttributeMaxDynamicSharedMemorySize, EP_SM);
    cudaFuncSetAttribute(pv_kernel,  cudaFuncAttributeMaxDynamicSharedMemorySize, EP_SM);
    cudaFuncSetAttribute(obj_kernel, cudaFuncAttributeMaxDynamicSharedMemorySize, OB_SM);

    prep_kernel<<<64, 256>>>(fr2_w, fr3_w, fr2pv_w, fr3pv_w, fo1_w, fo2_w, fo3_w);
    precompute_kernel<<<128, 256>>>(x, y, fr1_w, fr1_b, fr1pv_w, fr1pv_b);
    pp_kernel<<<152, 512, EP_SM>>>(fr2_b, fr3_b);
    pv_kernel<<<152, 512, EP_SM>>>(fr2pv_b, fr3pv_b);
    obj_kernel<<<128, 256, OB_SM>>>(x, fo1_b, fo2_b, fo3_b, fc_w, fc_b, out);
}

// round 9
// speedup vs baseline: 1.0547x; 1.0547x over previous
#include <cuda_runtime.h>
#include <stdint.h>

#define DI __device__ __forceinline__

// ===================== device scratch (no allocations) =====================
// U/V stored in pair-permuted channel order (see pairpos)
__device__ float g_Upp[128*64*128];
__device__ float g_Vpp[128*64*128];
__device__ float g_Upv[128*64*128];
__device__ float g_Vpv[128*14*128];
__device__ float g_EppT[128*64*64];   // transposed: [b][c][r]
__device__ float g_EpvT[128*64*64];   // transposed: [b][c][r]

// pre-transposed tf32 weight images, pair-permuted k, stride 136 (168 for FO1)
__device__ __align__(16) float g_W2pp[128*136];
__device__ __align__(16) float g_W3pp[64*136];
__device__ __align__(16) float g_W2pv[128*136];
__device__ __align__(16) float g_W3pv[64*136];
__device__ __align__(16) float g_FO1 [128*168];
__device__ __align__(16) float g_FO2 [128*136];
__device__ __align__(16) float g_FO3 [64*136];

// ===================== helpers =====================
DI float to_tf32(float x){ float r; asm("cvt.rna.tf32.f32 %0, %1;" : "=f"(r) : "f"(x)); return r; }
DI int pairpos(int k){ return (k & ~7) | (((k & 3) << 1) | ((k >> 2) & 1)); }
DI void barh(int id){ asm volatile("bar.sync %0, %1;" :: "r"(id), "r"(256) : "memory"); }

DI void mma_tf32(float* d, uint32_t a0, uint32_t a1, uint32_t a2, uint32_t a3,
                 uint32_t b0, uint32_t b1){
    asm volatile(
        "mma.sync.aligned.m16n8k8.row.col.f32.tf32.tf32.f32 "
        "{%0,%1,%2,%3}, {%4,%5,%6,%7}, {%8,%9}, {%0,%1,%2,%3};"
        : "+f"(d[0]), "+f"(d[1]), "+f"(d[2]), "+f"(d[3])
        : "r"(a0), "r"(a1), "r"(a2), "r"(a3), "r"(b0), "r"(b1));
}

// Warp GEMM on pair-interleaved tf32 buffers.
// MT m-tiles (16 rows at row0+mt*16) x NT n-tiles (8 cols from ncol0). acc[MT*NT*4].
template<int KT, int MT, int NT>
DI void wgemmp(const float* A, int sa, const float* W, int sw,
               int row0, int ncol0, int lane, float* acc)
{
    const int g = lane >> 2, tg = lane & 3;
#pragma unroll
    for (int i = 0; i < MT*NT*4; i++) acc[i] = 0.f;
#pragma unroll
    for (int kt = 0; kt < KT; kt++){
        const int jo = kt*8 + tg*2;
        float2 av[2*MT];
#pragma unroll
        for (int mt = 0; mt < MT; mt++){
            av[2*mt]   = *(const float2*)(A + (row0 + mt*16 + g)*sa + jo);
            av[2*mt+1] = *(const float2*)(A + (row0 + mt*16 + g + 8)*sa + jo);
        }
#pragma unroll
        for (int nt = 0; nt < NT; nt++){
            float2 bv = *(const float2*)(W + (ncol0 + nt*8 + g)*sw + jo);
#pragma unroll
            for (int mt = 0; mt < MT; mt++)
                mma_tf32(acc + (mt*NT+nt)*4,
                         __float_as_uint(av[2*mt].x),   __float_as_uint(av[2*mt+1].x),
                         __float_as_uint(av[2*mt].y),   __float_as_uint(av[2*mt+1].y),
                         __float_as_uint(bv.x),         __float_as_uint(bv.y));
        }
    }
}

// Epilogue: relu(acc+bias) -> tf32, stored pair-permuted into O (stride so)
template<int MT, int NT>
DI void epi_storep(const float* acc, float* O, int so,
                   int row0, int ncol0, int lane, const float* bias)
{
    const int g = lane >> 2, tg = lane & 3;
    const int p0 = pairpos(2*tg);
    const int p1 = pairpos(2*tg + 1);
#pragma unroll
    for (int mt = 0; mt < MT; mt++){
#pragma unroll
        for (int nt = 0; nt < NT; nt++){
            int cb = ncol0 + nt*8;
            float b0 = bias[cb + 2*tg], b1 = bias[cb + 2*tg + 1];
            const float* a = acc + (mt*NT+nt)*4;
            int r = row0 + mt*16 + g;
            O[r*so + cb + p0]     = to_tf32(fmaxf(a[0]+b0, 0.f));
            O[r*so + cb + p1]     = to_tf32(fmaxf(a[1]+b1, 0.f));
            O[(r+8)*so + cb + p0] = to_tf32(fmaxf(a[2]+b0, 0.f));
            O[(r+8)*so + cb + p1] = to_tf32(fmaxf(a[3]+b1, 0.f));
        }
    }
}

// ===================== prep: transpose + tf32 + pair-permute weights =====================
__global__ void prep_kernel(const float* __restrict__ w2pp, const float* __restrict__ w3pp,
                            const float* __restrict__ w2pv, const float* __restrict__ w3pv,
                            const float* __restrict__ w1o,  const float* __restrict__ w2o,
                            const float* __restrict__ w3o)
{
    int T = blockDim.x * gridDim.x, t0 = blockIdx.x * blockDim.x + threadIdx.x;
    for (int i = t0; i < 128*128; i += T){ int n = i>>7, k = i&127;
        g_W2pp[n*136 + pairpos(k)] = to_tf32(w2pp[k*128+n]); }
    for (int i = t0; i < 64*128; i += T){ int n = i>>7, k = i&127;
        g_W3pp[n*136 + pairpos(k)] = to_tf32(w3pp[k*64+n]); }
    for (int i = t0; i < 128*128; i += T){ int n = i>>7, k = i&127;
        g_W2pv[n*136 + pairpos(k)] = to_tf32(w2pv[k*128+n]); }
    for (int i = t0; i < 64*128; i += T){ int n = i>>7, k = i&127;
        g_W3pv[n*136 + pairpos(k)] = to_tf32(w3pv[k*64+n]); }
    for (int i = t0; i < 128*160; i += T){ int n = i/160, k = i - n*160;
        g_FO1[n*168 + pairpos(k)] = to_tf32(w1o[k*128+n]); }
    for (int i = t0; i < 128*128; i += T){ int n = i>>7, k = i&127;
        g_FO2[n*136 + pairpos(k)] = to_tf32(w2o[k*128+n]); }
    for (int i = t0; i < 64*128; i += T){ int n = i>>7, k = i&127;
        g_FO3[n*136 + pairpos(k)] = to_tf32(w3o[k*64+n]); }
}

// ===================== precompute: factorized first layers (fp32, pair-permuted out) ==========
__global__ void precompute_kernel(const float* __restrict__ x, const float* __restrict__ y,
                                  const float* __restrict__ w1,   const float* __restrict__ b1,
                                  const float* __restrict__ w1pv, const float* __restrict__ b1pv)
{
    __shared__ float xs[32][65];
    const int b = blockIdx.x, tid = threadIdx.x;
    for (int idx = tid; idx < 2048; idx += 256){
        int p = idx >> 6, n = idx & 63;
        xs[p][n] = x[(b*32 + p)*64 + n];
    }
    __syncthreads();
    for (int idx = tid; idx < 8192; idx += 256){
        int n = idx >> 7, h = idx & 127;
        float u = b1[h], v = 0.f, upv = b1pv[h];
#pragma unroll
        for (int p = 0; p < 32; p++){
            float xv = xs[p][n];
            u   = fmaf(xv, w1[p*128 + h], u);
            v   = fmaf(xv, w1[(32+p)*128 + h], v);
            upv = fmaf(xv, w1pv[p*128 + h], upv);
        }
        int ph = pairpos(h);
        g_Upp[(b*64+n)*128 + ph] = u;
        g_Vpp[(b*64+n)*128 + ph] = v;
        g_Upv[(b*64+n)*128 + ph] = upv;
    }
    for (int idx = tid; idx < 1792; idx += 256){
        int v = idx >> 7, h = idx & 127;
        float s = 0.f;
#pragma unroll
        for (int sv = 0; sv < 14; sv++)
            s = fmaf(y[(b*14+sv)*14 + v], w1pv[(32+sv)*128 + h], s);
        g_Vpv[(b*14+v)*128 + pairpos(h)] = s;
    }
}

// ===================== edge kernels: persistent, 512 thr, two half-CTAs =====================
// smem (bytes): W2[128x136] | W3[64x136] | BUF 2x[64x136] | b2 | b3 | part 2x128f
#define EP_W2   0
#define EP_W3   69632
#define EP_BUF  104448
#define EP_B2   174080
#define EP_B3   174592
#define EP_PT   174848
#define EP_SM   176896

__global__ __launch_bounds__(512, 1) void pp_kernel(const float* __restrict__ b2v,
                                                    const float* __restrict__ b3v)
{
    extern __shared__ char sm[];
    float* W2   = (float*)(sm + EP_W2);
    float* W3   = (float*)(sm + EP_W3);
    float* bias2= (float*)(sm + EP_B2);
    float* bias3= (float*)(sm + EP_B3);
    const int tid = threadIdx.x;
    const int half = tid >> 8, htid = tid & 255;
    const int hw = (tid >> 5) & 7, lane = tid & 31;
    const int g = lane >> 2, tg = lane & 3;
    const int rg = hw & 1, cg = hw >> 1;          // 2 row-groups x 4 col-groups (per half)
    float* BUF  = (float*)(sm + EP_BUF + half*34816);
    float* part = (float*)(sm + EP_PT  + half*512);
    const int barid = 1 + half;

    for (int i = tid; i < 4352; i += 512) ((float4*)W2)[i] = ((const float4*)g_W2pp)[i];
    for (int i = tid; i < 2176; i += 512) ((float4*)W3)[i] = ((const float4*)g_W3pp)[i];
    if (tid < 128) bias2[tid] = b2v[tid];
    if (tid < 64)  bias3[tid] = b3v[tid];
    __syncthreads();

    const int c4 = htid & 31;                     // float4 chunk within a 128-float row
    const int r0 = htid >> 5;                     // base row (8 rows per thread)
    const int hidx = blockIdx.x*2 + half, nh = gridDim.x*2;
    const int tstart = (int)((long long)8192*hidx/nh);
    const int tend   = (int)((long long)8192*(hidx+1)/nh);

    for (int t = tstart; t < tend; t++){
        const int b = t >> 6, r = t & 63;
        const float* Ur = g_Upp + ((size_t)b*64 + r)*128;
        const float* Vb = g_Vpp + (size_t)b*64*128;
        // build H1[s] = tf32(relu(U[r] + V[s])); permutation-invariant elementwise -> linear f4
        float4 u = *(const float4*)(Ur + c4*4);
#pragma unroll
        for (int it = 0; it < 8; it++){
            int s = r0 + it*8;
            float4 v = *(const float4*)(Vb + s*128 + c4*4);
            float4 h;
            h.x = to_tf32(fmaxf(u.x + v.x, 0.f));
            h.y = to_tf32(fmaxf(u.y + v.y, 0.f));
            h.z = to_tf32(fmaxf(u.z + v.z, 0.f));
            h.w = to_tf32(fmaxf(u.w + v.w, 0.f));
            *(float4*)(BUF + s*136 + c4*4) = h;
        }
        barh(barid);
        {   // layer 2: 64x128 in-place
            float acc[32];
            wgemmp<16,2,4>(BUF, 136, W2, 136, rg*32, cg*32, lane, acc);
            barh(barid);
            epi_storep<2,4>(acc, BUF, 136, rg*32, cg*32, lane, bias2);
        }
        barh(barid);
        {   // layer 3: 64x64 + self-excluded column reduce
            float acc3[16];
            wgemmp<16,2,2>(BUF, 136, W3, 136, rg*32, cg*16, lane, acc3);
#pragma unroll
            for (int nt = 0; nt < 2; nt++){
                int c = cg*16 + nt*8 + tg*2;
                float b0 = bias3[c], b1 = bias3[c+1];
                float t0 = 0.f, t1 = 0.f;
#pragma unroll
                for (int mt = 0; mt < 2; mt++){
                    int ra = rg*32 + mt*16 + g, rb = ra + 8;
                    bool z1 = (ra == r), z2 = (rb == r);
                    const float* a = acc3 + (mt*2+nt)*4;
                    t0 += (z1 ? 0.f : fmaxf(a[0]+b0, 0.f)) + (z2 ? 0.f : fmaxf(a[2]+b0, 0.f));
                    t1 += (z1 ? 0.f : fmaxf(a[1]+b1, 0.f)) + (z2 ? 0.f : fmaxf(a[3]+b1, 0.f));
                }
#pragma unroll
                for (int m = 4; m < 32; m <<= 1){
                    t0 += __shfl_xor_sync(0xffffffffu, t0, m);
                    t1 += __shfl_xor_sync(0xffffffffu, t1, m);
                }
                if (g == 0){ part[rg*64 + c] = t0; part[rg*64 + c + 1] = t1; }
            }
        }
        barh(barid);
        if (htid < 64){
            float ssum = part[htid] + part[64 + htid];
            g_EppT[((size_t)b*64 + htid)*64 + r] = ssum;
        }
        // no trailing barrier: part reads are >=2 barriers ahead of the next part write;
        // BUF writes of the next build are independent of part.
    }
}

__global__ __launch_bounds__(512, 1) void pv_kernel(const float* __restrict__ b2v,
                                                    const float* __restrict__ b3v)
{
    extern __shared__ char sm[];
    float* W2   = (float*)(sm + EP_W2);
    float* W3   = (float*)(sm + EP_W3);
    float* bias2= (float*)(sm + EP_B2);
    float* bias3= (float*)(sm + EP_B3);
    const int tid = threadIdx.x;
    const int half = tid >> 8, htid = tid & 255;
    const int hw = (tid >> 5) & 7, lane = tid & 31;
    const int g = lane >> 2, tg = lane & 3;
    const int rg = hw & 1, cg = hw >> 1;
    float* BUF = (float*)(sm + EP_BUF + half*34816);
    const int barid = 1 + half;

    for (int i = tid; i < 4352; i += 512) ((float4*)W2)[i] = ((const float4*)g_W2pv)[i];
    for (int i = tid; i < 2176; i += 512) ((float4*)W3)[i] = ((const float4*)g_W3pv)[i];
    if (tid < 128) bias2[tid] = b2v[tid];
    if (tid < 64)  bias3[tid] = b3v[tid];
    __syncthreads();

    const int c4 = htid & 31;
    const int r0 = htid >> 5;
    const int hidx = blockIdx.x*2 + half, nh = gridDim.x*2;
    const int tstart = (int)((long long)2048*hidx/nh);
    const int tend   = (int)((long long)2048*(hidx+1)/nh);

    for (int t = tstart; t < tend; t++){
        const int b = t >> 4, grp = t & 15;       // receivers grp*4 .. grp*4+3
        const float* Ub = g_Upv + ((size_t)b*64 + grp*4)*128;
        const float* Vb = g_Vpv + (size_t)b*14*128;
#pragma unroll
        for (int it = 0; it < 8; it++){
            int row = r0 + it*8;                  // ri = row>>4, vv = row&15
            int ri = row >> 4, vv = row & 15;
            float4 h; h.x = h.y = h.z = h.w = 0.f;
            if (vv < 14){
                float4 u = *(const float4*)(Ub + ri*128 + c4*4);
                float4 v = *(const float4*)(Vb + vv*128 + c4*4);
                h.x = to_tf32(fmaxf(u.x + v.x, 0.f));
                h.y = to_tf32(fmaxf(u.y + v.y, 0.f));
                h.z = to_tf32(fmaxf(u.z + v.z, 0.f));
                h.w = to_tf32(fmaxf(u.w + v.w, 0.f));
            }
            *(float4*)(BUF + row*136 + c4*4) = h;
        }
        barh(barid);
        {
            float acc[32];
            wgemmp<16,2,4>(BUF, 136, W2, 136, rg*32, cg*32, lane, acc);
            barh(barid);
            epi_storep<2,4>(acc, BUF, 136, rg*32, cg*32, lane, bias2);
        }
        barh(barid);
        {   // layer 3 + per-receiver reduce (receiver = grp*4 + rg*2 + mt)
            float acc3[16];
            wgemmp<16,2,2>(BUF, 136, W3, 136, rg*32, cg*16, lane, acc3);
            bool z2 = (g >= 6);                   // row vv=g+8 is pad when >=14
#pragma unroll
            for (int mt = 0; mt < 2; mt++){
                int recv = grp*4 + rg*2 + mt;
#pragma unroll
                for (int nt = 0; nt < 2; nt++){
                    int c = cg*16 + nt*8 + tg*2;
                    float b0 = bias3[c], b1 = bias3[c+1];
                    const float* a = acc3 + (mt*2+nt)*4;
                    float t0 = fmaxf(a[0]+b0, 0.f) + (z2 ? 0.f : fmaxf(a[2]+b0, 0.f));
                    float t1 = fmaxf(a[1]+b1, 0.f) + (z2 ? 0.f : fmaxf(a[3]+b1, 0.f));
#pragma unroll
                    for (int m = 4; m < 32; m <<= 1){
                        t0 += __shfl_xor_sync(0xffffffffu, t0, m);
                        t1 += __shfl_xor_sync(0xffffffffu, t1, m);
                    }
                    if (g == 0){
                        g_EpvT[((size_t)b*64 + c)*64 + recv]     = t0;
                        g_EpvT[((size_t)b*64 + c + 1)*64 + recv] = t1;
                    }
                }
            }
        }
        barh(barid);    // required: L3 reads BUF; next build writes BUF
    }
}

// ===================== object MLP + pool + classifier: 1 graph/block =====================
// C[64x168] (H3 overlays, stride 168) | Wbuf[128x168] | H2[64x136] | misc
#define OB_C   0
#define OB_W   43008
#define OB_H2  129024
#define OB_B1  163840
#define OB_B2  164352
#define OB_B3  164864
#define OB_FCB 165120
#define OB_PT  165152
#define OB_PL  165664
#define OB_SM  165920

__global__ __launch_bounds__(256) void obj_kernel(const float* __restrict__ x,
                                                  const float* __restrict__ b1v,
                                                  const float* __restrict__ b2v,
                                                  const float* __restrict__ b3v,
                                                  const float* __restrict__ fcw,
                                                  const float* __restrict__ fcb,
                                                  float* __restrict__ out)
{
    extern __shared__ char sm[];
    float* C    = (float*)(sm + OB_C);
    float* Wbuf = (float*)(sm + OB_W);
    float* H2   = (float*)(sm + OB_H2);
    float* H3   = (float*)(sm + OB_C);
    float* bias1  = (float*)(sm + OB_B1);
    float* bias2  = (float*)(sm + OB_B2);
    float* bias3  = (float*)(sm + OB_B3);
    float* fcbs   = (float*)(sm + OB_FCB);
    float* part   = (float*)(sm + OB_PT);
    float* pooled = (float*)(sm + OB_PL);
    const int tid = threadIdx.x, wid = tid >> 5, lane = tid & 31;
    const int g = lane >> 2, tg = lane & 3;
    const int rg = wid & 1, cg = wid >> 1;
    const int bg = blockIdx.x;

    for (int i = tid; i < 5376; i += 256) ((float4*)Wbuf)[i] = ((const float4*)g_FO1)[i];
    if (tid < 128) bias1[tid] = b1v[tid];
    if (tid < 128) bias2[tid] = b2v[tid];
    if (tid < 64)  bias3[tid] = b3v[tid];
    if (tid < 5)   fcbs[tid]  = fcb[tid];
    // C[n][pairpos(k)], K=160, stride 168
    for (int i = tid; i < 160*64; i += 256){
        int k = i >> 6, n = i & 63;
        float v;
        if (k < 32)      v = x[(bg*32 + k)*64 + n];
        else if (k < 96) v = g_EppT[((size_t)bg*64 + (k-32))*64 + n];
        else             v = g_EpvT[((size_t)bg*64 + (k-96))*64 + n];
        C[n*168 + pairpos(k)] = to_tf32(v);
    }
    __syncthreads();
    {   // layer 1
        float acc[32];
        wgemmp<20,2,4>(C, 168, Wbuf, 168, rg*32, cg*32, lane, acc);
        epi_storep<2,4>(acc, H2, 136, rg*32, cg*32, lane, bias1);
    }
    __syncthreads();
    for (int i = tid; i < 4352; i += 256) ((float4*)Wbuf)[i] = ((const float4*)g_FO2)[i];
    __syncthreads();
    {   // layer 2 (H3 overlays C, stride 168)
        float acc[32];
        wgemmp<16,2,4>(H2, 136, Wbuf, 136, rg*32, cg*32, lane, acc);
        __syncthreads();
        epi_storep<2,4>(acc, H3, 168, rg*32, cg*32, lane, bias2);
    }
    __syncthreads();
    for (int i = tid; i < 2176; i += 256) ((float4*)Wbuf)[i] = ((const float4*)g_FO3)[i];
    __syncthreads();
    {   // layer 3 + pooling reduce
        float acc[16];
        wgemmp<16,2,2>(H3, 168, Wbuf, 136, rg*32, cg*16, lane, acc);
#pragma unroll
        for (int nt = 0; nt < 2; nt++){
            int c = cg*16 + nt*8 + tg*2;
            float b0 = bias3[c], b1 = bias3[c+1];
            float t0 = 0.f, t1 = 0.f;
#pragma unroll
            for (int mt = 0; mt < 2; mt++){
                const float* a = acc + (mt*2+nt)*4;
                t0 += fmaxf(a[0]+b0, 0.f) + fmaxf(a[2]+b0, 0.f);
                t1 += fmaxf(a[1]+b1, 0.f) + fmaxf(a[3]+b1, 0.f);
            }
#pragma unroll
            for (int m = 4; m < 32; m <<= 1){
                t0 += __shfl_xor_sync(0xffffffffu, t0, m);
                t1 += __shfl_xor_sync(0xffffffffu, t1, m);
            }
            if (g == 0){ part[rg*64 + c] = t0; part[rg*64 + c + 1] = t1; }
        }
    }
    __syncthreads();
    if (tid < 64) pooled[tid] = part[tid] + part[64 + tid];
    __syncthreads();
    if (tid < 5){
        float s = fcbs[tid];
#pragma unroll 8
        for (int j = 0; j < 64; j++)
            s = fmaf(pooled[j], fcw[j*5 + tid], s);
        out[bg*5 + tid] = s;
    }
}

// ===================== launch =====================
extern "C" void kernel_launch(void* const* d_in, const int* in_sizes, int n_in,
                              void* d_out, int out_size)
{
    const float* x       = (const float*)d_in[0];
    const float* y       = (const float*)d_in[1];
    const float* fr1_w   = (const float*)d_in[2];
    const float* fr1_b   = (const float*)d_in[3];
    const float* fr2_w   = (const float*)d_in[4];
    const float* fr2_b   = (const float*)d_in[5];
    const float* fr3_w   = (const float*)d_in[6];
    const float* fr3_b   = (const float*)d_in[7];
    const float* fr1pv_w = (const float*)d_in[8];
    const float* fr1pv_b = (const float*)d_in[9];
    const float* fr2pv_w = (const float*)d_in[10];
    const float* fr2pv_b = (const float*)d_in[11];
    const float* fr3pv_w = (const float*)d_in[12];
    const float* fr3pv_b = (const float*)d_in[13];
    const float* fo1_w   = (const float*)d_in[14];
    const float* fo1_b   = (const float*)d_in[15];
    const float* fo2_w   = (const float*)d_in[16];
    const float* fo2_b   = (const float*)d_in[17];
    const float* fo3_w   = (const float*)d_in[18];
    const float* fo3_b   = (const float*)d_in[19];
    const float* fc_w    = (const float*)d_in[20];
    const float* fc_b    = (const float*)d_in[21];
    float* out = (float*)d_out;

    cudaFuncSetAttribute(pp_kernel,  cudaFuncAttributeMaxDynamicSharedMemorySize, EP_SM);
    cudaFuncSetAttribute(pv_kernel,  cudaFuncAttributeMaxDynamicSharedMemorySize, EP_SM);
    cudaFuncSetAttribute(obj_kernel, cudaFuncAttributeMaxDynamicSharedMemorySize, OB_SM);

    prep_kernel<<<64, 256>>>(fr2_w, fr3_w, fr2pv_w, fr3pv_w, fo1_w, fo2_w, fo3_w);
    precompute_kernel<<<128, 256>>>(x, y, fr1_w, fr1_b, fr1pv_w, fr1pv_b);
    pp_kernel<<<152, 512, EP_SM>>>(fr2_b, fr3_b);
    pv_kernel<<<152, 512, EP_SM>>>(fr2pv_b, fr3pv_b);
    obj_kernel<<<128, 256, OB_SM>>>(x, fo1_b, fo2_b, fo3_b, fc_w, fc_b, out);
}

// round 10
// speedup vs baseline: 1.6813x; 1.5942x over previous
#include <cuda_runtime.h>
#include <cuda_fp16.h>
#include <stdint.h>

#define DI __device__ __forceinline__

// ===================== device scratch (no allocations) =====================
// U/V stored fp32 in pp16-permuted channel order
__device__ float g_Upp[128*64*128];
__device__ float g_Vpp[128*64*128];
__device__ float g_Upv[128*64*128];
__device__ float g_Vpv[128*14*128];
__device__ float g_EppT[128*64*64];   // transposed: [b][c][r]
__device__ float g_EpvT[128*64*64];   // transposed: [b][c][r]

// pre-transposed fp16 weight images, pp16-permuted k, stride 144 halves (176 for FO1)
__device__ __align__(16) __half g_W2pp[128*144];
__device__ __align__(16) __half g_W3pp[64*144];
__device__ __align__(16) __half g_W2pv[128*144];
__device__ __align__(16) __half g_W3pv[64*144];
__device__ __align__(16) __half g_FO1 [128*176];
__device__ __align__(16) __half g_FO2 [128*144];
__device__ __align__(16) __half g_FO3 [64*144];

// ===================== helpers =====================
// 16-group channel permutation: fragment halves {k=2t, 2t+1, k+8, k+9} contiguous
DI int pp16(int k){
    return (k & ~15) | (((k & 7) >> 1) << 2) | (((k >> 3) & 1) << 1) | (k & 1);
}
DI void barh(int id){ asm volatile("bar.sync %0, %1;" :: "r"(id), "r"(256) : "memory"); }

DI void mma_fp16(float* d, uint32_t a0, uint32_t a1, uint32_t a2, uint32_t a3,
                 uint32_t b0, uint32_t b1){
    asm volatile(
        "mma.sync.aligned.m16n8k16.row.col.f32.f16.f16.f32 "
        "{%0,%1,%2,%3}, {%4,%5,%6,%7}, {%8,%9}, {%0,%1,%2,%3};"
        : "+f"(d[0]), "+f"(d[1]), "+f"(d[2]), "+f"(d[3])
        : "r"(a0), "r"(a1), "r"(a2), "r"(a3), "r"(b0), "r"(b1));
}

// Warp GEMM on pp16-interleaved fp16 buffers. KT = K/16.
// MT m-tiles (16 rows at row0+mt*16) x NT n-tiles (8 cols from ncol0). acc[MT*NT*4].
// Strides sa,sw in halves; (stride/2) mod 32 must avoid conflicts (144, 176 verified).
template<int KT, int MT, int NT>
DI void wgemm16(const __half* A, int sa, const __half* W, int sw,
                int row0, int ncol0, int lane, float* acc)
{
    const int g = lane >> 2, tg = lane & 3;
#pragma unroll
    for (int i = 0; i < MT*NT*4; i++) acc[i] = 0.f;
#pragma unroll
    for (int kt = 0; kt < KT; kt++){
        const int jo = kt*16 + tg*4;
        uint2 av[2*MT];
#pragma unroll
        for (int mt = 0; mt < MT; mt++){
            av[2*mt]   = *(const uint2*)(A + (row0 + mt*16 + g)*sa + jo);
            av[2*mt+1] = *(const uint2*)(A + (row0 + mt*16 + g + 8)*sa + jo);
        }
#pragma unroll
        for (int nt = 0; nt < NT; nt++){
            uint2 bv = *(const uint2*)(W + (ncol0 + nt*8 + g)*sw + jo);
#pragma unroll
            for (int mt = 0; mt < MT; mt++)
                mma_fp16(acc + (mt*NT+nt)*4,
                         av[2*mt].x, av[2*mt+1].x, av[2*mt].y, av[2*mt+1].y,
                         bv.x, bv.y);
        }
    }
}

// Epilogue: relu(acc+bias) -> fp16, stored pp16-permuted into O (stride so halves)
template<int MT, int NT>
DI void epi_store16(const float* acc, __half* O, int so,
                    int row0, int ncol0, int lane, const float* bias)
{
    const int g = lane >> 2, tg = lane & 3;
#pragma unroll
    for (int mt = 0; mt < MT; mt++){
#pragma unroll
        for (int nt = 0; nt < NT; nt++){
            int c0 = ncol0 + nt*8 + 2*tg;
            int q  = pp16(c0);                      // q even; q,q+1 adjacent
            float b0 = bias[c0], b1 = bias[c0+1];
            const float* a = acc + (mt*NT+nt)*4;
            int r = row0 + mt*16 + g;
            *(half2*)(O + r*so + q)     = __floats2half2_rn(fmaxf(a[0]+b0, 0.f), fmaxf(a[1]+b1, 0.f));
            *(half2*)(O + (r+8)*so + q) = __floats2half2_rn(fmaxf(a[2]+b0, 0.f), fmaxf(a[3]+b1, 0.f));
        }
    }
}

// ===================== prep: transpose + fp16 + pp16-permute weights =====================
__global__ void prep_kernel(const float* __restrict__ w2pp, const float* __restrict__ w3pp,
                            const float* __restrict__ w2pv, const float* __restrict__ w3pv,
                            const float* __restrict__ w1o,  const float* __restrict__ w2o,
                            const float* __restrict__ w3o)
{
    int T = blockDim.x * gridDim.x, t0 = blockIdx.x * blockDim.x + threadIdx.x;
    for (int i = t0; i < 128*128; i += T){ int n = i>>7, k = i&127;
        g_W2pp[n*144 + pp16(k)] = __float2half(w2pp[k*128+n]); }
    for (int i = t0; i < 64*128; i += T){ int n = i>>7, k = i&127;
        g_W3pp[n*144 + pp16(k)] = __float2half(w3pp[k*64+n]); }
    for (int i = t0; i < 128*128; i += T){ int n = i>>7, k = i&127;
        g_W2pv[n*144 + pp16(k)] = __float2half(w2pv[k*128+n]); }
    for (int i = t0; i < 64*128; i += T){ int n = i>>7, k = i&127;
        g_W3pv[n*144 + pp16(k)] = __float2half(w3pv[k*64+n]); }
    for (int i = t0; i < 128*160; i += T){ int n = i/160, k = i - n*160;
        g_FO1[n*176 + pp16(k)] = __float2half(w1o[k*128+n]); }
    for (int i = t0; i < 128*128; i += T){ int n = i>>7, k = i&127;
        g_FO2[n*144 + pp16(k)] = __float2half(w2o[k*128+n]); }
    for (int i = t0; i < 64*128; i += T){ int n = i>>7, k = i&127;
        g_FO3[n*144 + pp16(k)] = __float2half(w3o[k*64+n]); }
}

// ===================== precompute: factorized first layers (fp32, pp16-permuted out) ==========
__global__ void precompute_kernel(const float* __restrict__ x, const float* __restrict__ y,
                                  const float* __restrict__ w1,   const float* __restrict__ b1,
                                  const float* __restrict__ w1pv, const float* __restrict__ b1pv)
{
    __shared__ float xs[32][65];
    const int b = blockIdx.x, tid = threadIdx.x;
    for (int idx = tid; idx < 2048; idx += 256){
        int p = idx >> 6, n = idx & 63;
        xs[p][n] = x[(b*32 + p)*64 + n];
    }
    __syncthreads();
    for (int idx = tid; idx < 8192; idx += 256){
        int n = idx >> 7, h = idx & 127;
        float u = b1[h], v = 0.f, upv = b1pv[h];
#pragma unroll
        for (int p = 0; p < 32; p++){
            float xv = xs[p][n];
            u   = fmaf(xv, w1[p*128 + h], u);
            v   = fmaf(xv, w1[(32+p)*128 + h], v);
            upv = fmaf(xv, w1pv[p*128 + h], upv);
        }
        int ph = pp16(h);
        g_Upp[(b*64+n)*128 + ph] = u;
        g_Vpp[(b*64+n)*128 + ph] = v;
        g_Upv[(b*64+n)*128 + ph] = upv;
    }
    for (int idx = tid; idx < 1792; idx += 256){
        int v = idx >> 7, h = idx & 127;
        float s = 0.f;
#pragma unroll
        for (int sv = 0; sv < 14; sv++)
            s = fmaf(y[(b*14+sv)*14 + v], w1pv[(32+sv)*128 + h], s);
        g_Vpv[(b*14+v)*128 + pp16(h)] = s;
    }
}

// ===================== edge kernels: persistent, 512 thr, two half-CTAs, fp16 =====================
// smem (bytes): W2[128x144h] | W3[64x144h] | BUF 2x[64x144h] | b2 | b3 | part 2x128f
#define EP_W2   0
#define EP_W3   36864
#define EP_BUF  55296
#define EP_B2   92160
#define EP_B3   92672
#define EP_PT   92928
#define EP_SM   93952

__global__ __launch_bounds__(512, 1) void pp_kernel(const float* __restrict__ b2v,
                                                    const float* __restrict__ b3v)
{
    extern __shared__ char sm[];
    __half* W2   = (__half*)(sm + EP_W2);
    __half* W3   = (__half*)(sm + EP_W3);
    float* bias2 = (float*)(sm + EP_B2);
    float* bias3 = (float*)(sm + EP_B3);
    const int tid = threadIdx.x;
    const int half_ = tid >> 8, htid = tid & 255;
    const int hw = (tid >> 5) & 7, lane = tid & 31;
    const int g = lane >> 2, tg = lane & 3;
    const int rg = hw & 1, cg = hw >> 1;           // 2 row-groups x 4 col-groups per half
    __half* BUF = (__half*)(sm + EP_BUF + half_*18432);
    float* part = (float*)(sm + EP_PT  + half_*512);
    const int barid = 1 + half_;

    for (int i = tid; i < 2304; i += 512) ((float4*)W2)[i] = ((const float4*)g_W2pp)[i];
    for (int i = tid; i < 1152; i += 512) ((float4*)W3)[i] = ((const float4*)g_W3pp)[i];
    if (tid < 128) bias2[tid] = b2v[tid];
    if (tid < 64)  bias3[tid] = b3v[tid];
    __syncthreads();

    const int c4 = htid & 31;                      // 4-channel chunk within 128
    const int r0 = htid >> 5;                      // base row (8 rows/thread)
    const int hidx = blockIdx.x*2 + half_, nh = gridDim.x*2;
    const int tstart = (int)((long long)8192*hidx/nh);
    const int tend   = (int)((long long)8192*(hidx+1)/nh);

    for (int t = tstart; t < tend; t++){
        const int b = t >> 6, r = t & 63;
        const float* Ur = g_Upp + ((size_t)b*64 + r)*128;
        const float* Vb = g_Vpp + (size_t)b*64*128;
        // build H1[s] = fp16(relu(U[r]+V[s])); permutation-invariant elementwise
        float4 u = *(const float4*)(Ur + c4*4);
#pragma unroll
        for (int it = 0; it < 8; it++){
            int s = r0 + it*8;
            float4 v = *(const float4*)(Vb + s*128 + c4*4);
            half2 h0 = __floats2half2_rn(fmaxf(u.x+v.x, 0.f), fmaxf(u.y+v.y, 0.f));
            half2 h1 = __floats2half2_rn(fmaxf(u.z+v.z, 0.f), fmaxf(u.w+v.w, 0.f));
            uint2 o; o.x = *(uint32_t*)&h0; o.y = *(uint32_t*)&h1;
            *(uint2*)(BUF + s*144 + c4*4) = o;
        }
        barh(barid);
        {   // layer 2: 64x128 in-place
            float acc[32];
            wgemm16<8,2,4>(BUF, 144, W2, 144, rg*32, cg*32, lane, acc);
            barh(barid);
            epi_store16<2,4>(acc, BUF, 144, rg*32, cg*32, lane, bias2);
        }
        barh(barid);
        {   // layer 3: 64x64 + self-excluded column reduce
            float acc3[16];
            wgemm16<8,2,2>(BUF, 144, W3, 144, rg*32, cg*16, lane, acc3);
#pragma unroll
            for (int nt = 0; nt < 2; nt++){
                int c = cg*16 + nt*8 + tg*2;
                float b0 = bias3[c], b1 = bias3[c+1];
                float t0 = 0.f, t1 = 0.f;
#pragma unroll
                for (int mt = 0; mt < 2; mt++){
                    int ra = rg*32 + mt*16 + g, rb = ra + 8;
                    bool z1 = (ra == r), z2 = (rb == r);
                    const float* a = acc3 + (mt*2+nt)*4;
                    t0 += (z1 ? 0.f : fmaxf(a[0]+b0, 0.f)) + (z2 ? 0.f : fmaxf(a[2]+b0, 0.f));
                    t1 += (z1 ? 0.f : fmaxf(a[1]+b1, 0.f)) + (z2 ? 0.f : fmaxf(a[3]+b1, 0.f));
                }
#pragma unroll
                for (int m = 4; m < 32; m <<= 1){
                    t0 += __shfl_xor_sync(0xffffffffu, t0, m);
                    t1 += __shfl_xor_sync(0xffffffffu, t1, m);
                }
                if (g == 0){ part[rg*64 + c] = t0; part[rg*64 + c + 1] = t1; }
            }
        }
        barh(barid);
        if (htid < 64){
            float ssum = part[htid] + part[64 + htid];
            g_EppT[((size_t)b*64 + htid)*64 + r] = ssum;
        }
        // part reads are >=2 barriers ahead of the next part write; BUF independent
    }
}

__global__ __launch_bounds__(512, 1) void pv_kernel(const float* __restrict__ b2v,
                                                    const float* __restrict__ b3v)
{
    extern __shared__ char sm[];
    __half* W2   = (__half*)(sm + EP_W2);
    __half* W3   = (__half*)(sm + EP_W3);
    float* bias2 = (float*)(sm + EP_B2);
    float* bias3 = (float*)(sm + EP_B3);
    const int tid = threadIdx.x;
    const int half_ = tid >> 8, htid = tid & 255;
    const int hw = (tid >> 5) & 7, lane = tid & 31;
    const int g = lane >> 2, tg = lane & 3;
    const int rg = hw & 1, cg = hw >> 1;
    __half* BUF = (__half*)(sm + EP_BUF + half_*18432);
    const int barid = 1 + half_;

    for (int i = tid; i < 2304; i += 512) ((float4*)W2)[i] = ((const float4*)g_W2pv)[i];
    for (int i = tid; i < 1152; i += 512) ((float4*)W3)[i] = ((const float4*)g_W3pv)[i];
    if (tid < 128) bias2[tid] = b2v[tid];
    if (tid < 64)  bias3[tid] = b3v[tid];
    __syncthreads();

    const int c4 = htid & 31;
    const int r0 = htid >> 5;
    const int hidx = blockIdx.x*2 + half_, nh = gridDim.x*2;
    const int tstart = (int)((long long)2048*hidx/nh);
    const int tend   = (int)((long long)2048*(hidx+1)/nh);

    for (int t = tstart; t < tend; t++){
        const int b = t >> 4, grp = t & 15;        // receivers grp*4 .. grp*4+3
        const float* Ub = g_Upv + ((size_t)b*64 + grp*4)*128;
        const float* Vb = g_Vpv + (size_t)b*14*128;
#pragma unroll
        for (int it = 0; it < 8; it++){
            int row = r0 + it*8;                   // ri = row>>4, vv = row&15
            int ri = row >> 4, vv = row & 15;
            uint2 o; o.x = 0u; o.y = 0u;
            if (vv < 14){
                float4 u = *(const float4*)(Ub + ri*128 + c4*4);
                float4 v = *(const float4*)(Vb + vv*128 + c4*4);
                half2 h0 = __floats2half2_rn(fmaxf(u.x+v.x, 0.f), fmaxf(u.y+v.y, 0.f));
                half2 h1 = __floats2half2_rn(fmaxf(u.z+v.z, 0.f), fmaxf(u.w+v.w, 0.f));
                o.x = *(uint32_t*)&h0; o.y = *(uint32_t*)&h1;
            }
            *(uint2*)(BUF + row*144 + c4*4) = o;
        }
        barh(barid);
        {
            float acc[32];
            wgemm16<8,2,4>(BUF, 144, W2, 144, rg*32, cg*32, lane, acc);
            barh(barid);
            epi_store16<2,4>(acc, BUF, 144, rg*32, cg*32, lane, bias2);
        }
        barh(barid);
        {   // layer 3 + per-receiver reduce (receiver = grp*4 + rg*2 + mt)
            float acc3[16];
            wgemm16<8,2,2>(BUF, 144, W3, 144, rg*32, cg*16, lane, acc3);
            bool z2 = (g >= 6);                    // row vv=g+8 is pad when >=14
#pragma unroll
            for (int mt = 0; mt < 2; mt++){
                int recv = grp*4 + rg*2 + mt;
#pragma unroll
                for (int nt = 0; nt < 2; nt++){
                    int c = cg*16 + nt*8 + tg*2;
                    float b0 = bias3[c], b1 = bias3[c+1];
                    const float* a = acc3 + (mt*2+nt)*4;
                    float t0 = fmaxf(a[0]+b0, 0.f) + (z2 ? 0.f : fmaxf(a[2]+b0, 0.f));
                    float t1 = fmaxf(a[1]+b1, 0.f) + (z2 ? 0.f : fmaxf(a[3]+b1, 0.f));
#pragma unroll
                    for (int m = 4; m < 32; m <<= 1){
                        t0 += __shfl_xor_sync(0xffffffffu, t0, m);
                        t1 += __shfl_xor_sync(0xffffffffu, t1, m);
                    }
                    if (g == 0){
                        g_EpvT[((size_t)b*64 + c)*64 + recv]     = t0;
                        g_EpvT[((size_t)b*64 + c + 1)*64 + recv] = t1;
                    }
                }
            }
        }
        barh(barid);    // L3 reads BUF; next build writes BUF
    }
}

// ===================== object MLP + pool + classifier: 1 graph/block, fp16 =====================
// C[64x176h] (H3 overlays) | Wbuf[128x176h] (FO1->FO2->FO3) | H2[64x144h] | misc
#define OB_C   0
#define OB_W   22528
#define OB_H2  67584
#define OB_B1  86016
#define OB_B2  86528
#define OB_B3  87040
#define OB_FCB 87296
#define OB_PT  87328
#define OB_PL  87840
#define OB_SM  88096

__global__ __launch_bounds__(256) void obj_kernel(const float* __restrict__ x,
                                                  const float* __restrict__ b1v,
                                                  const float* __restrict__ b2v,
                                                  const float* __restrict__ b3v,
                                                  const float* __restrict__ fcw,
                                                  const float* __restrict__ fcb,
                                                  float* __restrict__ out)
{
    extern __shared__ char sm[];
    __half* C    = (__half*)(sm + OB_C);
    __half* Wbuf = (__half*)(sm + OB_W);
    __half* H2   = (__half*)(sm + OB_H2);
    __half* H3   = (__half*)(sm + OB_C);          // overlays C, stride 176
    float* bias1  = (float*)(sm + OB_B1);
    float* bias2  = (float*)(sm + OB_B2);
    float* bias3  = (float*)(sm + OB_B3);
    float* fcbs   = (float*)(sm + OB_FCB);
    float* part   = (float*)(sm + OB_PT);
    float* pooled = (float*)(sm + OB_PL);
    const int tid = threadIdx.x, wid = tid >> 5, lane = tid & 31;
    const int g = lane >> 2, tg = lane & 3;
    const int rg = wid & 1, cg = wid >> 1;
    const int bg = blockIdx.x;

    for (int i = tid; i < 2816; i += 256) ((float4*)Wbuf)[i] = ((const float4*)g_FO1)[i];
    if (tid < 128) bias1[tid] = b1v[tid];
    if (tid < 128) bias2[tid] = b2v[tid];
    if (tid < 64)  bias3[tid] = b3v[tid];
    if (tid < 5)   fcbs[tid]  = fcb[tid];
    // C[n][pp16(k)], K=160, stride 176
    for (int i = tid; i < 160*64; i += 256){
        int k = i >> 6, n = i & 63;
        float v;
        if (k < 32)      v = x[(bg*32 + k)*64 + n];
        else if (k < 96) v = g_EppT[((size_t)bg*64 + (k-32))*64 + n];
        else             v = g_EpvT[((size_t)bg*64 + (k-96))*64 + n];
        C[n*176 + pp16(k)] = __float2half(v);
    }
    __syncthreads();
    {   // layer 1
        float acc[32];
        wgemm16<10,2,4>(C, 176, Wbuf, 176, rg*32, cg*32, lane, acc);
        epi_store16<2,4>(acc, H2, 144, rg*32, cg*32, lane, bias1);
    }
    __syncthreads();
    for (int i = tid; i < 2304; i += 256) ((float4*)Wbuf)[i] = ((const float4*)g_FO2)[i];
    __syncthreads();
    {   // layer 2 (H3 overlays C, stride 176)
        float acc[32];
        wgemm16<8,2,4>(H2, 144, Wbuf, 144, rg*32, cg*32, lane, acc);
        __syncthreads();
        epi_store16<2,4>(acc, H3, 176, rg*32, cg*32, lane, bias2);
    }
    __syncthreads();
    for (int i = tid; i < 1152; i += 256) ((float4*)Wbuf)[i] = ((const float4*)g_FO3)[i];
    __syncthreads();
    {   // layer 3 + pooling reduce
        float acc[16];
        wgemm16<8,2,2>(H3, 176, Wbuf, 144, rg*32, cg*16, lane, acc);
#pragma unroll
        for (int nt = 0; nt < 2; nt++){
            int c = cg*16 + nt*8 + tg*2;
            float b0 = bias3[c], b1 = bias3[c+1];
            float t0 = 0.f, t1 = 0.f;
#pragma unroll
            for (int mt = 0; mt < 2; mt++){
                const float* a = acc + (mt*2+nt)*4;
                t0 += fmaxf(a[0]+b0, 0.f) + fmaxf(a[2]+b0, 0.f);
                t1 += fmaxf(a[1]+b1, 0.f) + fmaxf(a[3]+b1, 0.f);
            }
#pragma unroll
            for (int m = 4; m < 32; m <<= 1){
                t0 += __shfl_xor_sync(0xffffffffu, t0, m);
                t1 += __shfl_xor_sync(0xffffffffu, t1, m);
            }
            if (g == 0){ part[rg*64 + c] = t0; part[rg*64 + c + 1] = t1; }
        }
    }
    __syncthreads();
    if (tid < 64) pooled[tid] = part[tid] + part[64 + tid];
    __syncthreads();
    if (tid < 5){
        float s = fcbs[tid];
#pragma unroll 8
        for (int j = 0; j < 64; j++)
            s = fmaf(pooled[j], fcw[j*5 + tid], s);
        out[bg*5 + tid] = s;
    }
}

// ===================== launch =====================
extern "C" void kernel_launch(void* const* d_in, const int* in_sizes, int n_in,
                              void* d_out, int out_size)
{
    const float* x       = (const float*)d_in[0];
    const float* y       = (const float*)d_in[1];
    const float* fr1_w   = (const float*)d_in[2];
    const float* fr1_b   = (const float*)d_in[3];
    const float* fr2_w   = (const float*)d_in[4];
    const float* fr2_b   = (const float*)d_in[5];
    const float* fr3_w   = (const float*)d_in[6];
    const float* fr3_b   = (const float*)d_in[7];
    const float* fr1pv_w = (const float*)d_in[8];
    const float* fr1pv_b = (const float*)d_in[9];
    const float* fr2pv_w = (const float*)d_in[10];
    const float* fr2pv_b = (const float*)d_in[11];
    const float* fr3pv_w = (const float*)d_in[12];
    const float* fr3pv_b = (const float*)d_in[13];
    const float* fo1_w   = (const float*)d_in[14];
    const float* fo1_b   = (const float*)d_in[15];
    const float* fo2_w   = (const float*)d_in[16];
    const float* fo2_b   = (const float*)d_in[17];
    const float* fo3_w   = (const float*)d_in[18];
    const float* fo3_b   = (const float*)d_in[19];
    const float* fc_w    = (const float*)d_in[20];
    const float* fc_b    = (const float*)d_in[21];
    float* out = (float*)d_out;

    cudaFuncSetAttribute(pp_kernel,  cudaFuncAttributeMaxDynamicSharedMemorySize, EP_SM);
    cudaFuncSetAttribute(pv_kernel,  cudaFuncAttributeMaxDynamicSharedMemorySize, EP_SM);
    cudaFuncSetAttribute(obj_kernel, cudaFuncAttributeMaxDynamicSharedMemorySize, OB_SM);

    prep_kernel<<<64, 256>>>(fr2_w, fr3_w, fr2pv_w, fr3pv_w, fo1_w, fo2_w, fo3_w);
    precompute_kernel<<<128, 256>>>(x, y, fr1_w, fr1_b, fr1pv_w, fr1pv_b);
    pp_kernel<<<152, 512, EP_SM>>>(fr2_b, fr3_b);
    pv_kernel<<<152, 512, EP_SM>>>(fr2pv_b, fr3pv_b);
    obj_kernel<<<128, 256, OB_SM>>>(x, fo1_b, fo2_b, fo3_b, fc_w, fc_b, out);
}

// round 11
// speedup vs baseline: 1.7361x; 1.0325x over previous
#include <cuda_runtime.h>
#include <cuda_fp16.h>
#include <stdint.h>

#define DI __device__ __forceinline__

// ===================== device scratch (no allocations) =====================
// U/V stored fp32 in pp16-permuted channel order
__device__ float g_Upp[128*64*128];
__device__ float g_Vpp[128*64*128];
__device__ float g_Upv[128*64*128];
__device__ float g_Vpv[128*14*128];
__device__ float g_EppT[128*64*64];   // transposed: [b][c][r]
__device__ float g_EpvT[128*64*64];   // transposed: [b][c][r]

// pre-transposed fp16 weight images, pp16-permuted k, stride 144 halves (176 for FO1)
__device__ __align__(16) __half g_W2pp[128*144];
__device__ __align__(16) __half g_W3pp[64*144];
__device__ __align__(16) __half g_W2pv[128*144];
__device__ __align__(16) __half g_W3pv[64*144];
__device__ __align__(16) __half g_FO1 [128*176];
__device__ __align__(16) __half g_FO2 [128*144];
__device__ __align__(16) __half g_FO3 [64*144];

// ===================== helpers =====================
// 16-group channel permutation: fragment halves {2t, 2t+1, 2t+8, 2t+9} contiguous
DI int pp16(int k){
    return (k & ~15) | (((k & 7) >> 1) << 2) | (((k >> 3) & 1) << 1) | (k & 1);
}
DI void barh(int id){ asm volatile("bar.sync %0, %1;" :: "r"(id), "r"(256) : "memory"); }

DI void mma_fp16(float* d, uint32_t a0, uint32_t a1, uint32_t a2, uint32_t a3,
                 uint32_t b0, uint32_t b1){
    asm volatile(
        "mma.sync.aligned.m16n8k16.row.col.f32.f16.f16.f32 "
        "{%0,%1,%2,%3}, {%4,%5,%6,%7}, {%8,%9}, {%0,%1,%2,%3};"
        : "+f"(d[0]), "+f"(d[1]), "+f"(d[2]), "+f"(d[3])
        : "r"(a0), "r"(a1), "r"(a2), "r"(a3), "r"(b0), "r"(b1));
}

// Warp GEMM on pp16-interleaved fp16 buffers. KT = K/16.
template<int KT, int MT, int NT>
DI void wgemm16(const __half* A, int sa, const __half* W, int sw,
                int row0, int ncol0, int lane, float* acc)
{
    const int g = lane >> 2, tg = lane & 3;
#pragma unroll
    for (int i = 0; i < MT*NT*4; i++) acc[i] = 0.f;
#pragma unroll
    for (int kt = 0; kt < KT; kt++){
        const int jo = kt*16 + tg*4;
        uint2 av[2*MT];
#pragma unroll
        for (int mt = 0; mt < MT; mt++){
            av[2*mt]   = *(const uint2*)(A + (row0 + mt*16 + g)*sa + jo);
            av[2*mt+1] = *(const uint2*)(A + (row0 + mt*16 + g + 8)*sa + jo);
        }
#pragma unroll
        for (int nt = 0; nt < NT; nt++){
            uint2 bv = *(const uint2*)(W + (ncol0 + nt*8 + g)*sw + jo);
#pragma unroll
            for (int mt = 0; mt < MT; mt++)
                mma_fp16(acc + (mt*NT+nt)*4,
                         av[2*mt].x, av[2*mt+1].x, av[2*mt].y, av[2*mt+1].y,
                         bv.x, bv.y);
        }
    }
}

// Epilogue: relu(acc+bias) -> fp16, stored pp16-permuted into O (stride so halves)
template<int MT, int NT>
DI void epi_store16(const float* acc, __half* O, int so,
                    int row0, int ncol0, int lane, const float* bias)
{
    const int g = lane >> 2, tg = lane & 3;
#pragma unroll
    for (int mt = 0; mt < MT; mt++){
#pragma unroll
        for (int nt = 0; nt < NT; nt++){
            int c0 = ncol0 + nt*8 + 2*tg;
            int q  = pp16(c0);
            float b0 = bias[c0], b1 = bias[c0+1];
            const float* a = acc + (mt*NT+nt)*4;
            int r = row0 + mt*16 + g;
            *(half2*)(O + r*so + q)     = __floats2half2_rn(fmaxf(a[0]+b0, 0.f), fmaxf(a[1]+b1, 0.f));
            *(half2*)(O + (r+8)*so + q) = __floats2half2_rn(fmaxf(a[2]+b0, 0.f), fmaxf(a[3]+b1, 0.f));
        }
    }
}

// convert float4 pair-sum to packed 4 halves
DI uint2 pack4h(float4 u, float4 v){
    half2 h0 = __floats2half2_rn(fmaxf(u.x+v.x, 0.f), fmaxf(u.y+v.y, 0.f));
    half2 h1 = __floats2half2_rn(fmaxf(u.z+v.z, 0.f), fmaxf(u.w+v.w, 0.f));
    uint2 o; o.x = *(uint32_t*)&h0; o.y = *(uint32_t*)&h1;
    return o;
}

// ===================== prep: transpose + fp16 + pp16-permute weights =====================
__global__ void prep_kernel(const float* __restrict__ w2pp, const float* __restrict__ w3pp,
                            const float* __restrict__ w2pv, const float* __restrict__ w3pv,
                            const float* __restrict__ w1o,  const float* __restrict__ w2o,
                            const float* __restrict__ w3o)
{
    int T = blockDim.x * gridDim.x, t0 = blockIdx.x * blockDim.x + threadIdx.x;
    for (int i = t0; i < 128*128; i += T){ int n = i>>7, k = i&127;
        g_W2pp[n*144 + pp16(k)] = __float2half(w2pp[k*128+n]); }
    for (int i = t0; i < 64*128; i += T){ int n = i>>7, k = i&127;
        g_W3pp[n*144 + pp16(k)] = __float2half(w3pp[k*64+n]); }
    for (int i = t0; i < 128*128; i += T){ int n = i>>7, k = i&127;
        g_W2pv[n*144 + pp16(k)] = __float2half(w2pv[k*128+n]); }
    for (int i = t0; i < 64*128; i += T){ int n = i>>7, k = i&127;
        g_W3pv[n*144 + pp16(k)] = __float2half(w3pv[k*64+n]); }
    for (int i = t0; i < 128*160; i += T){ int n = i/160, k = i - n*160;
        g_FO1[n*176 + pp16(k)] = __float2half(w1o[k*128+n]); }
    for (int i = t0; i < 128*128; i += T){ int n = i>>7, k = i&127;
        g_FO2[n*144 + pp16(k)] = __float2half(w2o[k*128+n]); }
    for (int i = t0; i < 64*128; i += T){ int n = i>>7, k = i&127;
        g_FO3[n*144 + pp16(k)] = __float2half(w3o[k*64+n]); }
}

// ===================== precompute: factorized first layers (fp32, pp16-permuted out) ==========
__global__ void precompute_kernel(const float* __restrict__ x, const float* __restrict__ y,
                                  const float* __restrict__ w1,   const float* __restrict__ b1,
                                  const float* __restrict__ w1pv, const float* __restrict__ b1pv)
{
    __shared__ float xs[32][65];
    const int b = blockIdx.x, tid = threadIdx.x;
    for (int idx = tid; idx < 2048; idx += 256){
        int p = idx >> 6, n = idx & 63;
        xs[p][n] = x[(b*32 + p)*64 + n];
    }
    __syncthreads();
    for (int idx = tid; idx < 8192; idx += 256){
        int n = idx >> 7, h = idx & 127;
        float u = b1[h], v = 0.f, upv = b1pv[h];
#pragma unroll
        for (int p = 0; p < 32; p++){
            float xv = xs[p][n];
            u   = fmaf(xv, w1[p*128 + h], u);
            v   = fmaf(xv, w1[(32+p)*128 + h], v);
            upv = fmaf(xv, w1pv[p*128 + h], upv);
        }
        int ph = pp16(h);
        g_Upp[(b*64+n)*128 + ph] = u;
        g_Vpp[(b*64+n)*128 + ph] = v;
        g_Upv[(b*64+n)*128 + ph] = upv;
    }
    for (int idx = tid; idx < 1792; idx += 256){
        int v = idx >> 7, h = idx & 127;
        float s = 0.f;
#pragma unroll
        for (int sv = 0; sv < 14; sv++)
            s = fmaf(y[(b*14+sv)*14 + v], w1pv[(32+sv)*128 + h], s);
        g_Vpv[(b*14+v)*128 + pp16(h)] = s;
    }
}

// ===================== edge kernels: persistent, 512 thr, pipelined half-CTAs =====================
// smem: W2[128x144h] | W3[64x144h] | per-half {H1a,H1b,H2}[64x144h] x2 | b2 | b3 | part 2x128f
#define EP_W2   0
#define EP_W3   36864
#define EP_BUF  55296
#define EP_B2   165888
#define EP_B3   166400
#define EP_PT   166656
#define EP_SM   167680

__global__ __launch_bounds__(512, 1) void pp_kernel(const float* __restrict__ b2v,
                                                    const float* __restrict__ b3v)
{
    extern __shared__ char sm[];
    __half* W2   = (__half*)(sm + EP_W2);
    __half* W3   = (__half*)(sm + EP_W3);
    float* bias2 = (float*)(sm + EP_B2);
    float* bias3 = (float*)(sm + EP_B3);
    const int tid = threadIdx.x;
    const int half_ = tid >> 8, htid = tid & 255;
    const int hw = (tid >> 5) & 7, lane = tid & 31;
    const int g = lane >> 2, tg = lane & 3;
    const int rg = hw & 1, cg = hw >> 1;
    __half* H1a = (__half*)(sm + EP_BUF + half_*55296);
    __half* H1b = (__half*)(sm + EP_BUF + half_*55296 + 18432);
    __half* H2  = (__half*)(sm + EP_BUF + half_*55296 + 36864);
    float* part = (float*)(sm + EP_PT + half_*512);
    const int barid = 1 + half_;

    for (int i = tid; i < 2304; i += 512) ((float4*)W2)[i] = ((const float4*)g_W2pp)[i];
    for (int i = tid; i < 1152; i += 512) ((float4*)W3)[i] = ((const float4*)g_W3pp)[i];
    if (tid < 128) bias2[tid] = b2v[tid];
    if (tid < 64)  bias3[tid] = b3v[tid];
    __syncthreads();

    const int c4 = htid & 31;                    // 4-channel chunk within 128
    const int r0 = htid >> 5;                    // base row (8 rows/thread)
    const int hidx = blockIdx.x*2 + half_, nh = gridDim.x*2;
    const int tstart = (int)((long long)8192*hidx/nh);
    const int tend   = (int)((long long)8192*(hidx+1)/nh);

    __half* Hc = H1a;                            // current / next ping-pong
    __half* Hn = H1b;

    {   // prologue: build tile tstart into Hc
        const int b = tstart >> 6, r = tstart & 63;
        const float* Ur = g_Upp + ((size_t)b*64 + r)*128;
        const float* Vb = g_Vpp + (size_t)b*64*128;
        float4 u = *(const float4*)(Ur + c4*4);
#pragma unroll
        for (int it = 0; it < 8; it++){
            int s = r0 + it*8;
            float4 v = *(const float4*)(Vb + s*128 + c4*4);
            *(uint2*)(Hc + s*144 + c4*4) = pack4h(u, v);
        }
    }
    barh(barid);

    for (int t = tstart; t < tend; t++){
        {   // layer 2 -> H2 (separate buffer; no barrier needed before epi)
            float acc[32];
            wgemm16<8,2,4>(Hc, 144, W2, 144, rg*32, cg*32, lane, acc);
            epi_store16<2,4>(acc, H2, 144, rg*32, cg*32, lane, bias2);
        }
        barh(barid);                              // A: H2 visible to all

        // prefetch next tile's build (loads overlap the L3 GEMM below)
        const bool have_next = (t + 1 < tend);
        float4 u_n; float4 v_n[8];
        if (have_next){
            const int bn = (t+1) >> 6, rn = (t+1) & 63;
            const float* Ur = g_Upp + ((size_t)bn*64 + rn)*128;
            const float* Vb = g_Vpp + (size_t)bn*64*128;
            u_n = *(const float4*)(Ur + c4*4);
#pragma unroll
            for (int it = 0; it < 8; it++)
                v_n[it] = *(const float4*)(Vb + (r0 + it*8)*128 + c4*4);
        }

        float acc3[16];
        wgemm16<8,2,2>(H2, 144, W3, 144, rg*32, cg*16, lane, acc3);

        if (have_next){
#pragma unroll
            for (int it = 0; it < 8; it++)
                *(uint2*)(Hn + (r0 + it*8)*144 + c4*4) = pack4h(u_n, v_n[it]);
        }

        {   // self-excluded column reduce -> part
            const int r = t & 63;
#pragma unroll
            for (int nt = 0; nt < 2; nt++){
                int c = cg*16 + nt*8 + tg*2;
                float b0 = bias3[c], b1 = bias3[c+1];
                float t0 = 0.f, t1 = 0.f;
#pragma unroll
                for (int mt = 0; mt < 2; mt++){
                    int ra = rg*32 + mt*16 + g, rb = ra + 8;
                    bool z1 = (ra == r), z2 = (rb == r);
                    const float* a = acc3 + (mt*2+nt)*4;
                    t0 += (z1 ? 0.f : fmaxf(a[0]+b0, 0.f)) + (z2 ? 0.f : fmaxf(a[2]+b0, 0.f));
                    t1 += (z1 ? 0.f : fmaxf(a[1]+b1, 0.f)) + (z2 ? 0.f : fmaxf(a[3]+b1, 0.f));
                }
#pragma unroll
                for (int m = 4; m < 32; m <<= 1){
                    t0 += __shfl_xor_sync(0xffffffffu, t0, m);
                    t1 += __shfl_xor_sync(0xffffffffu, t1, m);
                }
                if (g == 0){ part[rg*64 + c] = t0; part[rg*64 + c + 1] = t1; }
            }
        }
        barh(barid);                              // E: part + Hn visible
        if (htid < 64){
            const int b = t >> 6, r = t & 63;
            g_EppT[((size_t)b*64 + htid)*64 + r] = part[htid] + part[64 + htid];
        }
        __half* tmp = Hc; Hc = Hn; Hn = tmp;
    }
}

__global__ __launch_bounds__(512, 1) void pv_kernel(const float* __restrict__ b2v,
                                                    const float* __restrict__ b3v)
{
    extern __shared__ char sm[];
    __half* W2   = (__half*)(sm + EP_W2);
    __half* W3   = (__half*)(sm + EP_W3);
    float* bias2 = (float*)(sm + EP_B2);
    float* bias3 = (float*)(sm + EP_B3);
    const int tid = threadIdx.x;
    const int half_ = tid >> 8, htid = tid & 255;
    const int hw = (tid >> 5) & 7, lane = tid & 31;
    const int g = lane >> 2, tg = lane & 3;
    const int rg = hw & 1, cg = hw >> 1;
    __half* H1a = (__half*)(sm + EP_BUF + half_*55296);
    __half* H1b = (__half*)(sm + EP_BUF + half_*55296 + 18432);
    __half* H2  = (__half*)(sm + EP_BUF + half_*55296 + 36864);
    const int barid = 1 + half_;

    for (int i = tid; i < 2304; i += 512) ((float4*)W2)[i] = ((const float4*)g_W2pv)[i];
    for (int i = tid; i < 1152; i += 512) ((float4*)W3)[i] = ((const float4*)g_W3pv)[i];
    if (tid < 128) bias2[tid] = b2v[tid];
    if (tid < 64)  bias3[tid] = b3v[tid];
    __syncthreads();

    const int c4 = htid & 31;
    const int r0 = htid >> 5;
    const int hidx = blockIdx.x*2 + half_, nh = gridDim.x*2;
    const int tstart = (int)((long long)2048*hidx/nh);
    const int tend   = (int)((long long)2048*(hidx+1)/nh);

    __half* Hc = H1a;
    __half* Hn = H1b;

    {   // prologue build: rows = 4 receivers x 16 slots (vv>=14 pad -> 0)
        const int b = tstart >> 4, grp = tstart & 15;
        const float* Ub = g_Upv + ((size_t)b*64 + grp*4)*128;
        const float* Vb = g_Vpv + (size_t)b*14*128;
#pragma unroll
        for (int it = 0; it < 8; it++){
            int row = r0 + it*8;
            int ri = row >> 4, vv = row & 15;
            uint2 o; o.x = 0u; o.y = 0u;
            if (vv < 14){
                float4 u = *(const float4*)(Ub + ri*128 + c4*4);
                float4 v = *(const float4*)(Vb + vv*128 + c4*4);
                o = pack4h(u, v);
            }
            *(uint2*)(Hc + row*144 + c4*4) = o;
        }
    }
    barh(barid);

    for (int t = tstart; t < tend; t++){
        {
            float acc[32];
            wgemm16<8,2,4>(Hc, 144, W2, 144, rg*32, cg*32, lane, acc);
            epi_store16<2,4>(acc, H2, 144, rg*32, cg*32, lane, bias2);
        }
        barh(barid);                              // A

        const bool have_next = (t + 1 < tend);
        float4 u_n[8]; float4 v_n[8]; bool valid[8];
        if (have_next){
            const int bn = (t+1) >> 4, gn = (t+1) & 15;
            const float* Ub = g_Upv + ((size_t)bn*64 + gn*4)*128;
            const float* Vb = g_Vpv + (size_t)bn*14*128;
#pragma unroll
            for (int it = 0; it < 8; it++){
                int row = r0 + it*8;
                int ri = row >> 4, vv = row & 15;
                valid[it] = (vv < 14);
                if (valid[it]){
                    u_n[it] = *(const float4*)(Ub + ri*128 + c4*4);
                    v_n[it] = *(const float4*)(Vb + vv*128 + c4*4);
                }
            }
        }

        float acc3[16];
        wgemm16<8,2,2>(H2, 144, W3, 144, rg*32, cg*16, lane, acc3);

        if (have_next){
#pragma unroll
            for (int it = 0; it < 8; it++){
                int row = r0 + it*8;
                uint2 o; o.x = 0u; o.y = 0u;
                if (valid[it]) o = pack4h(u_n[it], v_n[it]);
                *(uint2*)(Hn + row*144 + c4*4) = o;
            }
        }

        {   // per-receiver reduce (receiver = grp*4 + rg*2 + mt), direct to gmem
            const int b = t >> 4, grp = t & 15;
            bool z2 = (g >= 6);                   // row vv=g+8 pad when >=14
#pragma unroll
            for (int mt = 0; mt < 2; mt++){
                int recv = grp*4 + rg*2 + mt;
#pragma unroll
                for (int nt = 0; nt < 2; nt++){
                    int c = cg*16 + nt*8 + tg*2;
                    float b0 = bias3[c], b1 = bias3[c+1];
                    const float* a = acc3 + (mt*2+nt)*4;
                    float t0 = fmaxf(a[0]+b0, 0.f) + (z2 ? 0.f : fmaxf(a[2]+b0, 0.f));
                    float t1 = fmaxf(a[1]+b1, 0.f) + (z2 ? 0.f : fmaxf(a[3]+b1, 0.f));
#pragma unroll
                    for (int m = 4; m < 32; m <<= 1){
                        t0 += __shfl_xor_sync(0xffffffffu, t0, m);
                        t1 += __shfl_xor_sync(0xffffffffu, t1, m);
                    }
                    if (g == 0){
                        g_EpvT[((size_t)b*64 + c)*64 + recv]     = t0;
                        g_EpvT[((size_t)b*64 + c + 1)*64 + recv] = t1;
                    }
                }
            }
        }
        barh(barid);                              // E: Hn visible; H2 reads done
        __half* tmp = Hc; Hc = Hn; Hn = tmp;
    }
}

// ===================== object MLP + pool + classifier: 1 graph/block, fp16 =====================
#define OB_C   0
#define OB_W   22528
#define OB_H2  67584
#define OB_B1  86016
#define OB_B2  86528
#define OB_B3  87040
#define OB_FCB 87296
#define OB_PT  87328
#define OB_PL  87840
#define OB_SM  88096

__global__ __launch_bounds__(256) void obj_kernel(const float* __restrict__ x,
                                                  const float* __restrict__ b1v,
                                                  const float* __restrict__ b2v,
                                                  const float* __restrict__ b3v,
                                                  const float* __restrict__ fcw,
                                                  const float* __restrict__ fcb,
                                                  float* __restrict__ out)
{
    extern __shared__ char sm[];
    __half* C    = (__half*)(sm + OB_C);
    __half* Wbuf = (__half*)(sm + OB_W);
    __half* H2   = (__half*)(sm + OB_H2);
    __half* H3   = (__half*)(sm + OB_C);          // overlays C, stride 176
    float* bias1  = (float*)(sm + OB_B1);
    float* bias2  = (float*)(sm + OB_B2);
    float* bias3  = (float*)(sm + OB_B3);
    float* fcbs   = (float*)(sm + OB_FCB);
    float* part   = (float*)(sm + OB_PT);
    float* pooled = (float*)(sm + OB_PL);
    const int tid = threadIdx.x, wid = tid >> 5, lane = tid & 31;
    const int g = lane >> 2, tg = lane & 3;
    const int rg = wid & 1, cg = wid >> 1;
    const int bg = blockIdx.x;

    for (int i = tid; i < 2816; i += 256) ((float4*)Wbuf)[i] = ((const float4*)g_FO1)[i];
    if (tid < 128) bias1[tid] = b1v[tid];
    if (tid < 128) bias2[tid] = b2v[tid];
    if (tid < 64)  bias3[tid] = b3v[tid];
    if (tid < 5)   fcbs[tid]  = fcb[tid];
    for (int i = tid; i < 160*64; i += 256){
        int k = i >> 6, n = i & 63;
        float v;
        if (k < 32)      v = x[(bg*32 + k)*64 + n];
        else if (k < 96) v = g_EppT[((size_t)bg*64 + (k-32))*64 + n];
        else             v = g_EpvT[((size_t)bg*64 + (k-96))*64 + n];
        C[n*176 + pp16(k)] = __float2half(v);
    }
    __syncthreads();
    {   // layer 1
        float acc[32];
        wgemm16<10,2,4>(C, 176, Wbuf, 176, rg*32, cg*32, lane, acc);
        epi_store16<2,4>(acc, H2, 144, rg*32, cg*32, lane, bias1);
    }
    __syncthreads();
    for (int i = tid; i < 2304; i += 256) ((float4*)Wbuf)[i] = ((const float4*)g_FO2)[i];
    __syncthreads();
    {   // layer 2 (H3 overlays C, stride 176)
        float acc[32];
        wgemm16<8,2,4>(H2, 144, Wbuf, 144, rg*32, cg*32, lane, acc);
        __syncthreads();
        epi_store16<2,4>(acc, H3, 176, rg*32, cg*32, lane, bias2);
    }
    __syncthreads();
    for (int i = tid; i < 1152; i += 256) ((float4*)Wbuf)[i] = ((const float4*)g_FO3)[i];
    __syncthreads();
    {   // layer 3 + pooling reduce
        float acc[16];
        wgemm16<8,2,2>(H3, 176, Wbuf, 144, rg*32, cg*16, lane, acc);
#pragma unroll
        for (int nt = 0; nt < 2; nt++){
            int c = cg*16 + nt*8 + tg*2;
            float b0 = bias3[c], b1 = bias3[c+1];
            float t0 = 0.f, t1 = 0.f;
#pragma unroll
            for (int mt = 0; mt < 2; mt++){
                const float* a = acc + (mt*2+nt)*4;
                t0 += fmaxf(a[0]+b0, 0.f) + fmaxf(a[2]+b0, 0.f);
                t1 += fmaxf(a[1]+b1, 0.f) + fmaxf(a[3]+b1, 0.f);
            }
#pragma unroll
            for (int m = 4; m < 32; m <<= 1){
                t0 += __shfl_xor_sync(0xffffffffu, t0, m);
                t1 += __shfl_xor_sync(0xffffffffu, t1, m);
            }
            if (g == 0){ part[rg*64 + c] = t0; part[rg*64 + c + 1] = t1; }
        }
    }
    __syncthreads();
    if (tid < 64) pooled[tid] = part[tid] + part[64 + tid];
    __syncthreads();
    if (tid < 5){
        float s = fcbs[tid];
#pragma unroll 8
        for (int j = 0; j < 64; j++)
            s = fmaf(pooled[j], fcw[j*5 + tid], s);
        out[bg*5 + tid] = s;
    }
}

// ===================== launch =====================
extern "C" void kernel_launch(void* const* d_in, const int* in_sizes, int n_in,
                              void* d_out, int out_size)
{
    const float* x       = (const float*)d_in[0];
    const float* y       = (const float*)d_in[1];
    const float* fr1_w   = (const float*)d_in[2];
    const float* fr1_b   = (const float*)d_in[3];
    const float* fr2_w   = (const float*)d_in[4];
    const float* fr2_b   = (const float*)d_in[5];
    const float* fr3_w   = (const float*)d_in[6];
    const float* fr3_b   = (const float*)d_in[7];
    const float* fr1pv_w = (const float*)d_in[8];
    const float* fr1pv_b = (const float*)d_in[9];
    const float* fr2pv_w = (const float*)d_in[10];
    const float* fr2pv_b = (const float*)d_in[11];
    const float* fr3pv_w = (const float*)d_in[12];
    const float* fr3pv_b = (const float*)d_in[13];
    const float* fo1_w   = (const float*)d_in[14];
    const float* fo1_b   = (const float*)d_in[15];
    const float* fo2_w   = (const float*)d_in[16];
    const float* fo2_b   = (const float*)d_in[17];
    const float* fo3_w   = (const float*)d_in[18];
    const float* fo3_b   = (const float*)d_in[19];
    const float* fc_w    = (const float*)d_in[20];
    const float* fc_b    = (const float*)d_in[21];
    float* out = (float*)d_out;

    cudaFuncSetAttribute(pp_kernel,  cudaFuncAttributeMaxDynamicSharedMemorySize, EP_SM);
    cudaFuncSetAttribute(pv_kernel,  cudaFuncAttributeMaxDynamicSharedMemorySize, EP_SM);
    cudaFuncSetAttribute(obj_kernel, cudaFuncAttributeMaxDynamicSharedMemorySize, OB_SM);

    prep_kernel<<<64, 256>>>(fr2_w, fr3_w, fr2pv_w, fr3pv_w, fo1_w, fo2_w, fo3_w);
    precompute_kernel<<<128, 256>>>(x, y, fr1_w, fr1_b, fr1pv_w, fr1pv_b);
    pp_kernel<<<152, 512, EP_SM>>>(fr2_b, fr3_b);
    pv_kernel<<<152, 512, EP_SM>>>(fr2pv_b, fr3pv_b);
    obj_kernel<<<128, 256, OB_SM>>>(x, fo1_b, fo2_b, fo3_b, fc_w, fc_b, out);
}